// round 14
// baseline (speedup 1.0000x reference)
#include <cuda_runtime.h>
#include <cuda_fp16.h>

// x[32, 336, 32, 32] fp32, moving-avg k=25 (replicate pad), seasonal period 24
#define BB     32
#define CC     336
#define KS     25
#define PE     24
#define NG     (CC / PE)          // 14
#define HWW    1024
#define HW4    (HWW / 4)          // 256 float4 per (b,c) plane
#define NCOL4  (BB * HW4)         // 8192 float4-columns
#define NELEM  ((size_t)BB * CC * HWW)

#define COLS4   8                 // float4 columns per block
#define COLS4P  (COLS4 + 1)       // pad: de-conflict subsection rows
#define NTHREAD (COLS4 * NG)      // 112

__device__ __forceinline__ float4 f4_add(float4 a, float4 b) {
    return make_float4(a.x + b.x, a.y + b.y, a.z + b.z, a.w + b.w);
}
__device__ __forceinline__ float4 f4_sub(float4 a, float4 b) {
    return make_float4(a.x - b.x, a.y - b.y, a.z - b.z, a.w - b.w);
}
__device__ __forceinline__ float4 f4_scale(float4 a, float s) {
    return make_float4(a.x * s, a.y * s, a.z * s, a.w * s);
}

__global__ __launch_bounds__(NTHREAD, 6)   // 96-reg cap (measured ~-4%), 6 blocks/SM, 21 warps
void decomp_kernel(const float4* __restrict__ x,
                   float4* __restrict__ To,
                   float4* __restrict__ So,
                   float4* __restrict__ Ro)
{
    __shared__ __half2 xd_s[NG][PE][COLS4P][2];  // detrended, fp16 (~24 KB)
    __shared__ float4  acc[PE][COLS4];           // seasonal means, fp32 (3 KB)

    const int tx = threadIdx.x;             // [0,8) float4 column lane
    const int g  = threadIdx.y;             // [0,14) channel group
    const int col4 = blockIdx.x * COLS4 + tx;
    const int b   = col4 >> 8;
    const int hw4 = col4 & (HW4 - 1);

    const size_t base = (size_t)b * CC * HW4 + hw4;
    const float4* __restrict__ xp = x + base;

    const float inv_k = 1.0f / (float)KS;
    const float inv_g = 1.0f / (float)NG;
    const int   c0    = g * PE;

    // initial window sum at c = c0: sum_{j=-12..12} x[clamp(c0+j)]
    float4 wsum = make_float4(0.f, 0.f, 0.f, 0.f);
    #pragma unroll
    for (int j = -12; j <= 12; j++) {
        int cc = c0 + j;
        cc = cc < 0 ? 0 : (cc > CC - 1 ? CC - 1 : cc);
        wsum = f4_add(wsum, xp[(size_t)cc * HW4]);
    }

    // ---- Pass A: trend (write To), stash detrended (fp16) in smem ----
    #pragma unroll
    for (int p = 0; p < PE; p++) {
        const int c = c0 + p;
        float4 T  = f4_scale(wsum, inv_k);
        float4 xc = xp[(size_t)c * HW4];
        __stcs(&To[base + (size_t)c * HW4], T);   // evict-first: never re-read
        float4 xd = f4_sub(xc, T);
        xd_s[g][p][tx][0] = __floats2half2_rn(xd.x, xd.y);
        xd_s[g][p][tx][1] = __floats2half2_rn(xd.z, xd.w);
        int cin  = c + 13; if (cin  > CC - 1) cin  = CC - 1;
        int cout = c - 12; if (cout < 0)      cout = 0;
        wsum = f4_add(wsum, f4_sub(xp[(size_t)cin * HW4], xp[(size_t)cout * HW4]));
    }

    __syncthreads();

    // ---- Cross-group reduction (fp32 accumulate): each thread owns (p,t) pairs ----
    {
        const int tid = g * COLS4 + tx;
        #pragma unroll
        for (int idx = tid; idx < PE * COLS4; idx += NTHREAD) {
            const int p = idx >> 3;             // / COLS4
            const int t = idx & (COLS4 - 1);
            float2 s0 = make_float2(0.f, 0.f);
            float2 s1 = make_float2(0.f, 0.f);
            #pragma unroll
            for (int gg = 0; gg < NG; gg++) {
                float2 a0 = __half22float2(xd_s[gg][p][t][0]);
                float2 a1 = __half22float2(xd_s[gg][p][t][1]);
                s0.x += a0.x; s0.y += a0.y;
                s1.x += a1.x; s1.y += a1.y;
            }
            acc[p][t] = make_float4(s0.x * inv_g, s0.y * inv_g,
                                    s1.x * inv_g, s1.y * inv_g);
        }
    }

    __syncthreads();

    // ---- Pass B: emit seasonal + residual from smem (no global re-reads) ----
    #pragma unroll
    for (int p = 0; p < PE; p++) {
        const int c = c0 + p;
        float4 S  = acc[p][tx];
        float2 d0 = __half22float2(xd_s[g][p][tx][0]);
        float2 d1 = __half22float2(xd_s[g][p][tx][1]);
        float4 R  = make_float4(d0.x - S.x, d0.y - S.y, d1.x - S.z, d1.y - S.w);
        __stcs(&So[base + (size_t)c * HW4], S);
        __stcs(&Ro[base + (size_t)c * HW4], R);
    }
}

extern "C" void kernel_launch(void* const* d_in, const int* in_sizes, int n_in,
                              void* d_out, int out_size)
{
    const float4* x = (const float4*)d_in[0];
    float* out = (float*)d_out;
    float4* To = (float4*)out;
    float4* So = (float4*)(out + NELEM);
    float4* Ro = (float4*)(out + 2 * NELEM);
    dim3 blk(COLS4, NG);
    decomp_kernel<<<NCOL4 / COLS4, blk>>>(x, To, So, Ro);
}

// round 15
// speedup vs baseline: 1.0811x; 1.0811x over previous
#include <cuda_runtime.h>

// x[32, 336, 32, 32] fp32, moving-avg k=25 (replicate pad), seasonal period 24
#define BB     32
#define CC     336
#define KS     25
#define PE     24
#define NG     (CC / PE)          // 14
#define HWW    1024
#define HW4    (HWW / 4)          // 256 float4 per (b,c) plane
#define NCOL4  (BB * HW4)         // 8192 float4-columns
#define NELEM  ((size_t)BB * CC * HWW)

#define COLS4   8                 // float4 columns per block
#define NTHREAD (COLS4 * NG)      // 112

__device__ __forceinline__ float4 f4_add(float4 a, float4 b) {
    return make_float4(a.x + b.x, a.y + b.y, a.z + b.z, a.w + b.w);
}
__device__ __forceinline__ float4 f4_sub(float4 a, float4 b) {
    return make_float4(a.x - b.x, a.y - b.y, a.z - b.z, a.w - b.w);
}
__device__ __forceinline__ float4 f4_scale(float4 a, float s) {
    return make_float4(a.x * s, a.y * s, a.z * s, a.w * s);
}

__global__ __launch_bounds__(NTHREAD, 4)
void decomp_kernel(const float4* __restrict__ x,
                   float4* __restrict__ To,
                   float4* __restrict__ So,
                   float4* __restrict__ Ro)
{
    __shared__ float4 xd_s[NG][PE][COLS4];  // detrended values (42 KB)
    __shared__ float4 acc[PE][COLS4];       // seasonal means (1.5 KB)

    const int tx = threadIdx.x;             // [0,8) float4 column lane
    const int g  = threadIdx.y;             // [0,14) channel group
    const int col4 = blockIdx.x * COLS4 + tx;
    const int b   = col4 >> 8;
    const int hw4 = col4 & (HW4 - 1);

    // 32-bit offsets: max index = 32*336*256 < 2^23, well within int range
    const int base = b * (CC * HW4) + hw4;
    const float4* __restrict__ xp = x + base;

    const float inv_k = 1.0f / (float)KS;
    const float inv_g = 1.0f / (float)NG;
    const int   c0    = g * PE;

    // initial window sum at c = c0: sum_{j=-12..12} x[clamp(c0+j)]
    float4 wsum = make_float4(0.f, 0.f, 0.f, 0.f);
    #pragma unroll
    for (int j = -12; j <= 12; j++) {
        int cc = c0 + j;
        cc = cc < 0 ? 0 : (cc > CC - 1 ? CC - 1 : cc);
        wsum = f4_add(wsum, xp[cc * HW4]);
    }

    // ---- Pass A: trend (write To), stash detrended in smem ----
    #pragma unroll
    for (int p = 0; p < PE; p++) {
        const int c = c0 + p;
        float4 T  = f4_scale(wsum, inv_k);
        float4 xc = xp[c * HW4];
        __stcs(&To[base + c * HW4], T);        // evict-first: never re-read
        xd_s[g][p][tx] = f4_sub(xc, T);
        int cin  = c + 13; if (cin  > CC - 1) cin  = CC - 1;
        int cout = c - 12; if (cout < 0)      cout = 0;
        wsum = f4_add(wsum, f4_sub(xp[cin * HW4], xp[cout * HW4]));
    }

    __syncthreads();

    // ---- Cross-group reduction (no atomics): each thread owns (p, t) pairs ----
    {
        const int tid = g * COLS4 + tx;
        #pragma unroll
        for (int idx = tid; idx < PE * COLS4; idx += NTHREAD) {
            const int p = idx >> 3;            // / COLS4
            const int t = idx & (COLS4 - 1);
            float4 s = make_float4(0.f, 0.f, 0.f, 0.f);
            #pragma unroll
            for (int gg = 0; gg < NG; gg++) s = f4_add(s, xd_s[gg][p][t]);
            acc[p][t] = f4_scale(s, inv_g);
        }
    }

    __syncthreads();

    // ---- Pass B: emit seasonal + residual from smem (no global re-reads) ----
    #pragma unroll
    for (int p = 0; p < PE; p++) {
        const int c = c0 + p;
        float4 S  = acc[p][tx];
        float4 xd = xd_s[g][p][tx];
        __stcs(&So[base + c * HW4], S);
        __stcs(&Ro[base + c * HW4], f4_sub(xd, S));
    }
}

extern "C" void kernel_launch(void* const* d_in, const int* in_sizes, int n_in,
                              void* d_out, int out_size)
{
    const float4* x = (const float4*)d_in[0];
    float* out = (float*)d_out;
    float4* To = (float4*)out;
    float4* So = (float4*)(out + NELEM);
    float4* Ro = (float4*)(out + 2 * NELEM);
    dim3 blk(COLS4, NG);
    decomp_kernel<<<NCOL4 / COLS4, blk>>>(x, To, So, Ro);
}

// round 16
// speedup vs baseline: 1.0822x; 1.0010x over previous
#include <cuda_runtime.h>

// x[32, 336, 32, 32] fp32, moving-avg k=25 (replicate pad), seasonal period 24
#define BB     32
#define CC     336
#define KS     25
#define PE     24
#define NG     (CC / PE)          // 14
#define HWW    1024
#define HW4    (HWW / 4)          // 256 float4 per (b,c) plane
#define NCOL4  (BB * HW4)         // 8192 float4-columns
#define NELEM  ((size_t)BB * CC * HWW)

#define COLS4   8                 // float4 columns per block
#define NTHREAD (COLS4 * NG)      // 112
#define RING    13                // xc ring: x[c0+p] = cin(p-13) for p>=13

__device__ __forceinline__ float4 f4_add(float4 a, float4 b) {
    return make_float4(a.x + b.x, a.y + b.y, a.z + b.z, a.w + b.w);
}
__device__ __forceinline__ float4 f4_sub(float4 a, float4 b) {
    return make_float4(a.x - b.x, a.y - b.y, a.z - b.z, a.w - b.w);
}
__device__ __forceinline__ float4 f4_scale(float4 a, float s) {
    return make_float4(a.x * s, a.y * s, a.z * s, a.w * s);
}

__global__ __launch_bounds__(NTHREAD, 4)
void decomp_kernel(const float4* __restrict__ x,
                   float4* __restrict__ To,
                   float4* __restrict__ So,
                   float4* __restrict__ Ro)
{
    __shared__ float4 xd_s[NG][PE][COLS4];  // detrended values (42 KB)
    __shared__ float4 acc[PE][COLS4];       // seasonal means (1.5 KB)

    const int tx = threadIdx.x;             // [0,8) float4 column lane
    const int g  = threadIdx.y;             // [0,14) channel group
    const int col4 = blockIdx.x * COLS4 + tx;
    const int b   = col4 >> 8;
    const int hw4 = col4 & (HW4 - 1);

    // 32-bit offsets: max index = 32*336*256 < 2^23
    const int base = b * (CC * HW4) + hw4;
    const float4* __restrict__ xp = x + base;

    const float inv_k = 1.0f / (float)KS;
    const float inv_g = 1.0f / (float)NG;
    const int   c0    = g * PE;

    // ---- Init: 25-load batch for window sum; W[j] keeps x[c0+j] (j=0..12) ----
    float4 W[RING];
    float4 wsum = make_float4(0.f, 0.f, 0.f, 0.f);
    #pragma unroll
    for (int j = -12; j <= 12; j++) {
        int cc = c0 + j;
        cc = cc < 0 ? 0 : (cc > CC - 1 ? CC - 1 : cc);
        float4 v = xp[cc * HW4];
        wsum = f4_add(wsum, v);
        if (j >= 0) W[j] = v;               // static slot under full unroll
    }

    // ---- Pass A: trend (write To), stash detrended in smem; xc from ring ----
    #pragma unroll
    for (int p = 0; p < PE; p++) {
        const int c = c0 + p;
        float4 T  = f4_scale(wsum, inv_k);
        float4 xc = W[p % RING];            // x[c0+p], no load
        __stcs(&To[base + c * HW4], T);     // evict-first: never re-read
        xd_s[g][p][tx] = f4_sub(xc, T);

        int cin  = c + 13; if (cin  > CC - 1) cin  = CC - 1;
        int cout = c - 12; if (cout < 0)      cout = 0;
        float4 vin  = xp[cin  * HW4];       // fresh load (prefetchable, independent)
        float4 vout = xp[cout * HW4];       // L1 hit (init-window address)
        wsum = f4_add(wsum, f4_sub(vin, vout));
        W[p % RING] = vin;                  // becomes xc at step p+13
    }

    __syncthreads();

    // ---- Cross-group reduction (no atomics): each thread owns (p, t) pairs ----
    {
        const int tid = g * COLS4 + tx;
        #pragma unroll
        for (int idx = tid; idx < PE * COLS4; idx += NTHREAD) {
            const int p = idx >> 3;            // / COLS4
            const int t = idx & (COLS4 - 1);
            float4 s = make_float4(0.f, 0.f, 0.f, 0.f);
            #pragma unroll
            for (int gg = 0; gg < NG; gg++) s = f4_add(s, xd_s[gg][p][t]);
            acc[p][t] = f4_scale(s, inv_g);
        }
    }

    __syncthreads();

    // ---- Pass B: emit seasonal + residual from smem (no global re-reads) ----
    #pragma unroll
    for (int p = 0; p < PE; p++) {
        const int c = c0 + p;
        float4 S  = acc[p][tx];
        float4 xd = xd_s[g][p][tx];
        __stcs(&So[base + c * HW4], S);
        __stcs(&Ro[base + c * HW4], f4_sub(xd, S));
    }
}

extern "C" void kernel_launch(void* const* d_in, const int* in_sizes, int n_in,
                              void* d_out, int out_size)
{
    const float4* x = (const float4*)d_in[0];
    float* out = (float*)d_out;
    float4* To = (float4*)out;
    float4* So = (float4*)(out + NELEM);
    float4* Ro = (float4*)(out + 2 * NELEM);
    dim3 blk(COLS4, NG);
    decomp_kernel<<<NCOL4 / COLS4, blk>>>(x, To, So, Ro);
}